// round 1
// baseline (speedup 1.0000x reference)
#include <cuda_runtime.h>
#include <cuda_bf16.h>
#include <cstdint>

// Problem constants
#define BATCH   16384
#define TT      10      // tokens per sequence
#define DD      64      // model dim
#define HH      4       // heads
#define DH      16      // head dim
#define LL      3       // layers
#define FF      256     // ffn dim
#define NSEQ    16      // sequences per CTA
#define MM      (NSEQ*TT)   // 160 activation rows per CTA
#define NTHREADS 256

// Shared memory layout (floats)
#define H_STR   65          // padded stride for h
#define B_STR   257         // padded stride for buf
#define H_ELEMS (MM*H_STR)          // 10400
#define B_ELEMS (MM*B_STR)          // 41120
#define W_ELEMS (64*64)             // 4096
#define SMEM_FLOATS (H_ELEMS + B_ELEMS + W_ELEMS)
#define SMEM_BYTES  (SMEM_FLOATS*4) // 222464

// ---------------- packed f32x2 helpers ----------------
__device__ __forceinline__ void fma2(unsigned long long &d,
                                     unsigned long long a,
                                     unsigned long long b) {
#if __CUDA_ARCH__ >= 1000
    asm("fma.rn.f32x2 %0, %1, %2, %0;" : "+l"(d) : "l"(a), "l"(b));
#else
    float2 dv = *reinterpret_cast<float2*>(&d);
    float2 av = *reinterpret_cast<float2*>(&a);
    float2 bv = *reinterpret_cast<float2*>(&b);
    dv.x = fmaf(av.x, bv.x, dv.x);
    dv.y = fmaf(av.y, bv.y, dv.y);
    d = *reinterpret_cast<unsigned long long*>(&dv);
#endif
}

__device__ __forceinline__ unsigned long long bcast2(float a) {
    unsigned long long r;
    asm("mov.b64 %0, {%1, %1};" : "=l"(r) : "f"(a));
    return r;
}

__device__ __forceinline__ float2 unpack2(unsigned long long v) {
    float2 f;
    asm("mov.b64 {%0, %1}, %2;" : "=f"(f.x), "=f"(f.y) : "l"(v));
    return f;
}

__device__ __forceinline__ float gelu_exact(float v) {
    return 0.5f * v * (1.0f + erff(v * 0.70710678118654752f));
}

// ---------------- weight tile prefetch (64x64) ----------------
struct WFrag { float4 v[4]; };

__device__ __forceinline__ WFrag fetch_w64(const float* __restrict__ g, int gStride) {
    WFrag f;
    int t = threadIdx.x;
#pragma unroll
    for (int i = 0; i < 4; i++) {
        int e  = t + i * NTHREADS;      // 0..1023
        int k  = e >> 4;                // row 0..63
        int c4 = e & 15;                // float4 index in row
        f.v[i] = *reinterpret_cast<const float4*>(g + k * gStride + c4 * 4);
    }
    return f;
}

__device__ __forceinline__ void commit_w64(const WFrag& f, float* __restrict__ ws) {
    int t = threadIdx.x;
#pragma unroll
    for (int i = 0; i < 4; i++) {
        int e  = t + i * NTHREADS;
        int k  = e >> 4;
        int c4 = e & 15;
        *reinterpret_cast<float4*>(ws + k * 64 + c4 * 4) = f.v[i];
    }
}

// ---------------- GEMM tile: [160 x 64] = A[160 x 64] * W[64 x 64] ----------------
// Thread tile: 5 rows x 8 cols, thread grid 32 x 8.
__device__ __forceinline__ void gemm_tile(
    const float* __restrict__ Asm, int aStr,
    const float* __restrict__ ws,
    float* __restrict__ Osm, int oStr,
    const float* __restrict__ bias,   // global ptr or nullptr
    bool doGelu, bool doAcc)
{
    const int tr = threadIdx.x >> 3;  // 0..31
    const int tc = threadIdx.x & 7;   // 0..7
    const float* A0 = Asm + (tr * 5) * aStr;
    const ulonglong2* W2 = reinterpret_cast<const ulonglong2*>(ws) + tc * 2;

    unsigned long long acc[5][4];
#pragma unroll
    for (int u = 0; u < 5; u++)
#pragma unroll
        for (int j = 0; j < 4; j++) acc[u][j] = 0ULL;

#pragma unroll 8
    for (int k = 0; k < 64; k++) {
        unsigned long long av[5];
#pragma unroll
        for (int u = 0; u < 5; u++) av[u] = bcast2(A0[u * aStr + k]);
        ulonglong2 b0 = W2[k * 16];
        ulonglong2 b1 = W2[k * 16 + 1];
#pragma unroll
        for (int u = 0; u < 5; u++) {
            fma2(acc[u][0], av[u], b0.x);
            fma2(acc[u][1], av[u], b0.y);
            fma2(acc[u][2], av[u], b1.x);
            fma2(acc[u][3], av[u], b1.y);
        }
    }

    const int c0 = tc * 8;
#pragma unroll
    for (int u = 0; u < 5; u++) {
        float* orow = Osm + (tr * 5 + u) * oStr + c0;
#pragma unroll
        for (int j = 0; j < 4; j++) {
            float2 v = unpack2(acc[u][j]);
            float x0 = v.x, x1 = v.y;
            if (bias) {
                x0 += bias[c0 + 2 * j];
                x1 += bias[c0 + 2 * j + 1];
            }
            if (doGelu) { x0 = gelu_exact(x0); x1 = gelu_exact(x1); }
            if (doAcc)  { orow[2 * j] += x0; orow[2 * j + 1] += x1; }
            else        { orow[2 * j]  = x0; orow[2 * j + 1]  = x1; }
        }
    }
}

// ---------------- layernorm over 64, thread-per-row ----------------
__device__ __forceinline__ void layernorm_rows(
    const float* __restrict__ src, int sStr,
    float* __restrict__ dst, int dStr,
    const float* __restrict__ g, const float* __restrict__ b)
{
    int t = threadIdx.x;
    if (t < MM) {
        const float* r = src + t * sStr;
        float s = 0.f, s2 = 0.f;
#pragma unroll 16
        for (int d = 0; d < DD; d++) { float v = r[d]; s += v; s2 += v * v; }
        float m   = s * (1.f / DD);
        float var = s2 * (1.f / DD) - m * m;
        float inv = rsqrtf(var + 1e-5f);
        float* o = dst + t * dStr;
#pragma unroll 16
        for (int d = 0; d < DD; d++)
            o[d] = (r[d] - m) * inv * g[d] + b[d];
    }
}

__global__ __launch_bounds__(NTHREADS, 1)
void waypoint_kernel(
    const float* __restrict__ x,
    const float* __restrict__ embed_w, const float* __restrict__ embed_b,
    const float* __restrict__ ln1_g,   const float* __restrict__ ln1_b,
    const float* __restrict__ qkv_w,   const float* __restrict__ proj_w,
    const float* __restrict__ ln2_g,   const float* __restrict__ ln2_b,
    const float* __restrict__ ffn_w1,  const float* __restrict__ ffn_b1,
    const float* __restrict__ ffn_w2,  const float* __restrict__ ffn_b2,
    const float* __restrict__ lnf_g,   const float* __restrict__ lnf_b,
    const float* __restrict__ head_w,  const float* __restrict__ head_b,
    float* __restrict__ out)
{
    extern __shared__ float sm[];
    float* h   = sm;                 // [160][65]
    float* buf = sm + H_ELEMS;       // [160][257]
    float* ws  = buf + B_ELEMS;      // [64][64]

    const int tid = threadIdx.x;
    const int rowBase = blockIdx.x * MM;   // global token row base

    // -------- embed: h = x @ embed_w + embed_b --------
    {
        const float4* X4 = reinterpret_cast<const float4*>(x);
        for (int idx = tid; idx < MM * DD; idx += NTHREADS) {
            int r = idx >> 6, d = idx & 63;
            float4 xv = X4[rowBase + r];
            float v = embed_b[d];
            v = fmaf(xv.x, embed_w[d],        v);
            v = fmaf(xv.y, embed_w[64 + d],   v);
            v = fmaf(xv.z, embed_w[128 + d],  v);
            v = fmaf(xv.w, embed_w[192 + d],  v);
            h[r * H_STR + d] = v;
        }
    }
    __syncthreads();

    // Prefetch first weight tile: layer 0 qkv, N-tile 0
    WFrag wf = fetch_w64(qkv_w, 3 * DD);

    for (int i = 0; i < LL; i++) {
        const float* l_qkv = qkv_w  + i * DD * 3 * DD;
        const float* l_prj = proj_w + i * DD * DD;
        const float* l_w1  = ffn_w1 + i * DD * FF;
        const float* l_w2  = ffn_w2 + i * FF * DD;

        // -------- ln1 -> buf[:,192:256] --------
        layernorm_rows(h, H_STR, buf + 192, B_STR, ln1_g + i * DD, ln1_b + i * DD);
        __syncthreads();

        // -------- qkv: buf[:,0:192] = ln1 @ qkv_w --------
        for (int nt = 0; nt < 3; nt++) {
            commit_w64(wf, ws);
            __syncthreads();
            // prefetch next tile
            if (nt < 2)  wf = fetch_w64(l_qkv + (nt + 1) * 64, 3 * DD);
            else         wf = fetch_w64(l_prj, DD);
            gemm_tile(buf + 192, B_STR, ws, buf + nt * 64, B_STR, nullptr, false, false);
            __syncthreads();
        }

        // -------- attention (causal, T=10, dh=16) --------
        {
            int pair = tid >> 2;       // 0..63 : (seq, head)
            int sub  = tid & 3;
            int s  = pair >> 2;        // 0..15
            int hd = pair & 3;         // 0..3
            const float* qb = buf + hd * DH;
            const float* kb = buf + 64  + hd * DH;
            const float* vb = buf + 128 + hd * DH;
            float* yb = buf + 192 + hd * DH;

            for (int q = sub; q < TT; q += 4) {
                int rq = s * TT + q;
                float qv[DH];
#pragma unroll
                for (int d = 0; d < DH; d++) qv[d] = qb[rq * B_STR + d];

                float sc[TT];
                float mx = -1e30f;
                for (int kk = 0; kk <= q; kk++) {
                    const float* kr = kb + (s * TT + kk) * B_STR;
                    float a = 0.f;
#pragma unroll
                    for (int d = 0; d < DH; d++) a = fmaf(qv[d], kr[d], a);
                    a *= 0.25f;           // dh^-0.5
                    sc[kk] = a;
                    mx = fmaxf(mx, a);
                }
                float ssum = 0.f;
                for (int kk = 0; kk <= q; kk++) {
                    sc[kk] = expf(sc[kk] - mx);
                    ssum += sc[kk];
                }
                float inv = 1.f / ssum;
                float y[DH];
#pragma unroll
                for (int d = 0; d < DH; d++) y[d] = 0.f;
                for (int kk = 0; kk <= q; kk++) {
                    float a = sc[kk] * inv;
                    const float* vr = vb + (s * TT + kk) * B_STR;
#pragma unroll
                    for (int d = 0; d < DH; d++) y[d] = fmaf(a, vr[d], y[d]);
                }
                float* yo = yb + rq * B_STR;
#pragma unroll
                for (int d = 0; d < DH; d++) yo[d] = y[d];
            }
        }
        __syncthreads();

        // -------- proj: h += y @ proj_w --------
        commit_w64(wf, ws);
        __syncthreads();
        wf = fetch_w64(l_w1, FF);   // prefetch ffn_w1 tile 0
        gemm_tile(buf + 192, B_STR, ws, h, H_STR, nullptr, false, true);
        __syncthreads();

        // -------- ln2 -> buf[:,0:64] --------
        layernorm_rows(h, H_STR, buf, B_STR, ln2_g + i * DD, ln2_b + i * DD);
        __syncthreads();

        // -------- FFN, N tiled in 4 chunks of 64 --------
        for (int ft = 0; ft < 4; ft++) {
            // z_tile = gelu(ln2 @ w1_tile + b1_tile) -> buf[:,64:128]
            commit_w64(wf, ws);
            __syncthreads();
            wf = fetch_w64(l_w2 + ft * 64 * DD, DD);  // prefetch matching w2 rows
            gemm_tile(buf, B_STR, ws, buf + 64, B_STR,
                      ffn_b1 + i * FF + ft * 64, true, false);
            __syncthreads();

            // h += z_tile @ w2_rows (+ b2 once)
            commit_w64(wf, ws);
            __syncthreads();
            if (ft < 3)      wf = fetch_w64(l_w1 + (ft + 1) * 64, FF);
            else if (i < 2)  wf = fetch_w64(qkv_w + (i + 1) * DD * 3 * DD, 3 * DD);
            else             wf = fetch_w64(qkv_w, 3 * DD);   // harmless tail prefetch
            gemm_tile(buf + 64, B_STR, ws, h, H_STR,
                      (ft == 0) ? (ffn_b2 + i * DD) : nullptr, false, true);
            __syncthreads();
        }
    }

    // -------- final layernorm -> buf[:,0:64] --------
    layernorm_rows(h, H_STR, buf, B_STR, lnf_g, lnf_b);
    __syncthreads();

    // -------- head: out[s, j] = lnf(h)[last token] @ head_w + head_b --------
    if (tid < NSEQ * 10) {
        int s = tid / 10;
        int j = tid % 10;
        const float* r = buf + (s * TT + TT - 1) * B_STR;
        float a = head_b[j];
#pragma unroll 16
        for (int d = 0; d < DD; d++) a = fmaf(r[d], head_w[d * 10 + j], a);
        out[(blockIdx.x * NSEQ + s) * 10 + j] = a;
    }
}

extern "C" void kernel_launch(void* const* d_in, const int* in_sizes, int n_in,
                              void* d_out, int out_size)
{
    const float* x       = (const float*)d_in[0];
    const float* embed_w = (const float*)d_in[1];
    const float* embed_b = (const float*)d_in[2];
    const float* ln1_g   = (const float*)d_in[3];
    const float* ln1_b   = (const float*)d_in[4];
    const float* qkv_w   = (const float*)d_in[5];
    const float* proj_w  = (const float*)d_in[6];
    const float* ln2_g   = (const float*)d_in[7];
    const float* ln2_b   = (const float*)d_in[8];
    const float* ffn_w1  = (const float*)d_in[9];
    const float* ffn_b1  = (const float*)d_in[10];
    const float* ffn_w2  = (const float*)d_in[11];
    const float* ffn_w2b = (const float*)d_in[12];
    const float* lnf_g   = (const float*)d_in[13];
    const float* lnf_b   = (const float*)d_in[14];
    const float* head_w  = (const float*)d_in[15];
    const float* head_b  = (const float*)d_in[16];
    float* out = (float*)d_out;

    int nTokens = in_sizes[0] / 4;       // B*T
    int nB = nTokens / TT;
    int grid = nB / NSEQ;                // 1024

    cudaFuncSetAttribute(waypoint_kernel,
                         cudaFuncAttributeMaxDynamicSharedMemorySize, SMEM_BYTES);

    waypoint_kernel<<<grid, NTHREADS, SMEM_BYTES>>>(
        x, embed_w, embed_b, ln1_g, ln1_b, qkv_w, proj_w,
        ln2_g, ln2_b, ffn_w1, ffn_b1, ffn_w2, ffn_w2b,
        lnf_g, lnf_b, head_w, head_b, out);
}

// round 2
// speedup vs baseline: 1.3127x; 1.3127x over previous
#include <cuda_runtime.h>
#include <cuda_bf16.h>
#include <cstdint>

// Problem constants
#define BATCH   16384
#define TT      10      // tokens per sequence
#define DD      64      // model dim
#define HH      4       // heads
#define DH      16      // head dim
#define LL      3       // layers
#define FF      256     // ffn dim
#define NSEQ    16      // sequences per CTA
#define MM      (NSEQ*TT)   // 160 activation rows per CTA
#define NTHREADS 512

// Shared memory layout (floats) — all strides multiple of 4 (16B alignment)
#define H_STR   68
#define B_STR   260
#define W_STR   66          // Wt stride: 66 mod 32 = 2 -> conflict-free LDS.64
#define H_ELEMS (MM*H_STR)          // 10880
#define B_ELEMS (MM*B_STR)          // 41600
#define W_ELEMS (64*W_STR)          // 4224
#define SMEM_FLOATS (H_ELEMS + B_ELEMS + W_ELEMS)
#define SMEM_BYTES  (SMEM_FLOATS*4) // 226816

// ---------------- packed f32x2 helpers ----------------
__device__ __forceinline__ void fma2(unsigned long long &d,
                                     unsigned long long a,
                                     unsigned long long b) {
    asm("fma.rn.f32x2 %0, %1, %2, %0;" : "+l"(d) : "l"(a), "l"(b));
}

__device__ __forceinline__ float2 unpack2(unsigned long long v) {
    float2 f;
    asm("mov.b64 {%0, %1}, %2;" : "=f"(f.x), "=f"(f.y) : "l"(v));
    return f;
}

__device__ __forceinline__ float gelu_exact(float v) {
    return 0.5f * v * (1.0f + erff(v * 0.70710678118654752f));
}

// ---------------- weight tile prefetch (64x64) ----------------
struct WFrag { float4 v[2]; };

__device__ __forceinline__ WFrag fetch_w64(const float* __restrict__ g, int gStride) {
    WFrag f;
    int t = threadIdx.x;
#pragma unroll
    for (int i = 0; i < 2; i++) {
        int e  = t + i * NTHREADS;      // 0..1023
        int k  = e >> 4;                // row 0..63
        int c4 = e & 15;                // float4 index in row
        f.v[i] = *reinterpret_cast<const float4*>(g + k * gStride + c4 * 4);
    }
    return f;
}

// Commit transposed: Wt[j][k] = W[k][j], stride W_STR
__device__ __forceinline__ void commit_wt(const WFrag& f, float* __restrict__ wt) {
    int t = threadIdx.x;
#pragma unroll
    for (int i = 0; i < 2; i++) {
        int e  = t + i * NTHREADS;
        int k  = e >> 4;
        int j0 = (e & 15) * 4;
        wt[(j0 + 0) * W_STR + k] = f.v[i].x;
        wt[(j0 + 1) * W_STR + k] = f.v[i].y;
        wt[(j0 + 2) * W_STR + k] = f.v[i].z;
        wt[(j0 + 3) * W_STR + k] = f.v[i].w;
    }
}

// ---------------- GEMM tile: [160 x 64] = A[160 x 64] * W[64 x 64] ----------------
// 512 threads: tr = tid>>4 (0..31) -> 5 rows each; tc = tid&15 -> cols {tc,tc+16,tc+32,tc+48}
// acc.x accumulates even k, acc.y odd k; horizontal add at the end.
__device__ __forceinline__ void gemm_tile(
    const float* __restrict__ Asm, int aStr,
    const float* __restrict__ wt,
    float* __restrict__ Osm, int oStr,
    const float* __restrict__ bias,   // global ptr or nullptr
    bool doGelu, bool doAcc)
{
    const int tr = threadIdx.x >> 4;  // 0..31
    const int tc = threadIdx.x & 15;  // 0..15
    const float* A0 = Asm + (tr * 5) * aStr;

    unsigned long long acc[5][4];
#pragma unroll
    for (int u = 0; u < 5; u++)
#pragma unroll
        for (int c = 0; c < 4; c++) acc[u][c] = 0ULL;

#pragma unroll 4
    for (int k4 = 0; k4 < 16; k4++) {
        unsigned long long a0[5], a1[5];
#pragma unroll
        for (int u = 0; u < 5; u++) {
            ulonglong2 av = *reinterpret_cast<const ulonglong2*>(A0 + u * aStr + k4 * 4);
            a0[u] = av.x;   // k = 4k4, 4k4+1
            a1[u] = av.y;   // k = 4k4+2, 4k4+3
        }
#pragma unroll
        for (int c = 0; c < 4; c++) {
            const float* wr = wt + (tc + 16 * c) * W_STR + k4 * 4;
            unsigned long long w0 = *reinterpret_cast<const unsigned long long*>(wr);
            unsigned long long w1 = *reinterpret_cast<const unsigned long long*>(wr + 2);
#pragma unroll
            for (int u = 0; u < 5; u++) {
                fma2(acc[u][c], a0[u], w0);
                fma2(acc[u][c], a1[u], w1);
            }
        }
    }

#pragma unroll
    for (int u = 0; u < 5; u++) {
        float* orow = Osm + (tr * 5 + u) * oStr;
#pragma unroll
        for (int c = 0; c < 4; c++) {
            int j = tc + 16 * c;
            float2 v = unpack2(acc[u][c]);
            float x = v.x + v.y;
            if (bias)   x += bias[j];
            if (doGelu) x = gelu_exact(x);
            if (doAcc)  orow[j] += x;
            else        orow[j]  = x;
        }
    }
}

// ---------------- layernorm over 64, thread-per-row, vectorized ----------------
__device__ __forceinline__ void layernorm_rows(
    const float* __restrict__ src, int sStr,
    float* __restrict__ dst, int dStr,
    const float* __restrict__ g, const float* __restrict__ b)
{
    int t = threadIdx.x;
    if (t < MM) {
        const float4* r4 = reinterpret_cast<const float4*>(src + t * sStr);
        float s = 0.f, s2 = 0.f;
        float4 rv[16];
#pragma unroll
        for (int i = 0; i < 16; i++) {
            float4 v = r4[i];
            rv[i] = v;
            s  += v.x + v.y + v.z + v.w;
            s2 += v.x * v.x + v.y * v.y + v.z * v.z + v.w * v.w;
        }
        float m   = s * (1.f / DD);
        float var = s2 * (1.f / DD) - m * m;
        float inv = rsqrtf(var + 1e-5f);
        float4* o4 = reinterpret_cast<float4*>(dst + t * dStr);
        const float4* g4 = reinterpret_cast<const float4*>(g);
        const float4* b4 = reinterpret_cast<const float4*>(b);
#pragma unroll
        for (int i = 0; i < 16; i++) {
            float4 gv = g4[i], bv = b4[i], v = rv[i];
            float4 o;
            o.x = (v.x - m) * inv * gv.x + bv.x;
            o.y = (v.y - m) * inv * gv.y + bv.y;
            o.z = (v.z - m) * inv * gv.z + bv.z;
            o.w = (v.w - m) * inv * gv.w + bv.w;
            o4[i] = o;
        }
    }
}

__global__ __launch_bounds__(NTHREADS, 1)
void waypoint_kernel(
    const float* __restrict__ x,
    const float* __restrict__ embed_w, const float* __restrict__ embed_b,
    const float* __restrict__ ln1_g,   const float* __restrict__ ln1_b,
    const float* __restrict__ qkv_w,   const float* __restrict__ proj_w,
    const float* __restrict__ ln2_g,   const float* __restrict__ ln2_b,
    const float* __restrict__ ffn_w1,  const float* __restrict__ ffn_b1,
    const float* __restrict__ ffn_w2,  const float* __restrict__ ffn_b2,
    const float* __restrict__ lnf_g,   const float* __restrict__ lnf_b,
    const float* __restrict__ head_w,  const float* __restrict__ head_b,
    float* __restrict__ out)
{
    extern __shared__ float sm[];
    float* h   = sm;                 // [160][68]
    float* buf = sm + H_ELEMS;       // [160][260]
    float* wt  = buf + B_ELEMS;      // [64][66] transposed weight tile

    const int tid = threadIdx.x;
    const int rowBase = blockIdx.x * MM;

    // -------- embed: h = x @ embed_w + embed_b --------
    {
        const float4* X4 = reinterpret_cast<const float4*>(x);
        const float4* W4 = reinterpret_cast<const float4*>(embed_w);
        const float4* B4 = reinterpret_cast<const float4*>(embed_b);
        for (int idx = tid; idx < MM * 16; idx += NTHREADS) {
            int r = idx >> 4, d4 = idx & 15;
            float4 xv = X4[rowBase + r];
            float4 w0 = W4[d4], w1 = W4[16 + d4], w2 = W4[32 + d4], w3 = W4[48 + d4];
            float4 v = B4[d4];
            v.x = fmaf(xv.x, w0.x, fmaf(xv.y, w1.x, fmaf(xv.z, w2.x, fmaf(xv.w, w3.x, v.x))));
            v.y = fmaf(xv.x, w0.y, fmaf(xv.y, w1.y, fmaf(xv.z, w2.y, fmaf(xv.w, w3.y, v.y))));
            v.z = fmaf(xv.x, w0.z, fmaf(xv.y, w1.z, fmaf(xv.z, w2.z, fmaf(xv.w, w3.z, v.z))));
            v.w = fmaf(xv.x, w0.w, fmaf(xv.y, w1.w, fmaf(xv.z, w2.w, fmaf(xv.w, w3.w, v.w))));
            *reinterpret_cast<float4*>(h + r * H_STR + d4 * 4) = v;
        }
    }
    __syncthreads();

    // Prefetch first weight tile: layer 0 qkv, N-tile 0
    WFrag wf = fetch_w64(qkv_w, 3 * DD);

    for (int i = 0; i < LL; i++) {
        const float* l_qkv = qkv_w  + i * DD * 3 * DD;
        const float* l_prj = proj_w + i * DD * DD;
        const float* l_w1  = ffn_w1 + i * DD * FF;
        const float* l_w2  = ffn_w2 + i * FF * DD;

        // -------- ln1 -> buf[:,192:256] --------
        layernorm_rows(h, H_STR, buf + 192, B_STR, ln1_g + i * DD, ln1_b + i * DD);
        __syncthreads();

        // -------- qkv: buf[:,0:192] = ln1 @ qkv_w --------
        for (int nt = 0; nt < 3; nt++) {
            commit_wt(wf, wt);
            __syncthreads();
            if (nt < 2)  wf = fetch_w64(l_qkv + (nt + 1) * 64, 3 * DD);
            else         wf = fetch_w64(l_prj, DD);
            gemm_tile(buf + 192, B_STR, wt, buf + nt * 64, B_STR, nullptr, false, false);
            __syncthreads();
        }

        // -------- attention (causal, T=10, dh=16) --------
        {
            int pair = tid >> 3;       // 0..63 : (seq, head)
            int sub  = tid & 7;
            int s  = pair >> 2;        // 0..15
            int hd = pair & 3;         // 0..3
            const float* qb = buf + hd * DH;
            const float* kb = buf + 64  + hd * DH;
            const float* vb = buf + 128 + hd * DH;
            float* yb = buf + 192 + hd * DH;

            for (int q = sub; q < TT; q += 8) {
                int rq = s * TT + q;
                float qv[DH];
#pragma unroll
                for (int d = 0; d < DH; d++) qv[d] = qb[rq * B_STR + d];

                float sc[TT];
                float mx = -1e30f;
                for (int kk = 0; kk <= q; kk++) {
                    const float* kr = kb + (s * TT + kk) * B_STR;
                    float a = 0.f;
#pragma unroll
                    for (int d = 0; d < DH; d++) a = fmaf(qv[d], kr[d], a);
                    a *= 0.25f;           // dh^-0.5
                    sc[kk] = a;
                    mx = fmaxf(mx, a);
                }
                float ssum = 0.f;
                for (int kk = 0; kk <= q; kk++) {
                    sc[kk] = expf(sc[kk] - mx);
                    ssum += sc[kk];
                }
                float inv = 1.f / ssum;
                float y[DH];
#pragma unroll
                for (int d = 0; d < DH; d++) y[d] = 0.f;
                for (int kk = 0; kk <= q; kk++) {
                    float a = sc[kk] * inv;
                    const float* vr = vb + (s * TT + kk) * B_STR;
#pragma unroll
                    for (int d = 0; d < DH; d++) y[d] = fmaf(a, vr[d], y[d]);
                }
                float* yo = yb + rq * B_STR;
#pragma unroll
                for (int d = 0; d < DH; d++) yo[d] = y[d];
            }
        }
        __syncthreads();

        // -------- proj: h += y @ proj_w --------
        commit_wt(wf, wt);
        __syncthreads();
        wf = fetch_w64(l_w1, FF);   // prefetch ffn_w1 tile 0
        gemm_tile(buf + 192, B_STR, wt, h, H_STR, nullptr, false, true);
        __syncthreads();

        // -------- ln2 -> buf[:,0:64] --------
        layernorm_rows(h, H_STR, buf, B_STR, ln2_g + i * DD, ln2_b + i * DD);
        __syncthreads();

        // -------- FFN, N tiled in 4 chunks of 64 --------
        for (int ft = 0; ft < 4; ft++) {
            // z_tile = gelu(ln2 @ w1_tile + b1_tile) -> buf[:,64:128]
            commit_wt(wf, wt);
            __syncthreads();
            wf = fetch_w64(l_w2 + ft * 64 * DD, DD);  // matching w2 rows
            gemm_tile(buf, B_STR, wt, buf + 64, B_STR,
                      ffn_b1 + i * FF + ft * 64, true, false);
            __syncthreads();

            // h += z_tile @ w2_rows (+ b2 once)
            commit_wt(wf, wt);
            __syncthreads();
            if (ft < 3)      wf = fetch_w64(l_w1 + (ft + 1) * 64, FF);
            else if (i < 2)  wf = fetch_w64(qkv_w + (i + 1) * DD * 3 * DD, 3 * DD);
            else             wf = fetch_w64(qkv_w, 3 * DD);   // harmless tail
            gemm_tile(buf + 64, B_STR, wt, h, H_STR,
                      (ft == 0) ? (ffn_b2 + i * DD) : nullptr, false, true);
            __syncthreads();
        }
    }

    // -------- final layernorm -> buf[:,0:64] --------
    layernorm_rows(h, H_STR, buf, B_STR, lnf_g, lnf_b);
    __syncthreads();

    // -------- head: out[s, j] = lnf(h)[last token] @ head_w + head_b --------
    if (tid < NSEQ * 10) {
        int s = tid / 10;
        int j = tid % 10;
        const float* r = buf + (s * TT + TT - 1) * B_STR;
        float a = head_b[j];
#pragma unroll 16
        for (int d = 0; d < DD; d++) a = fmaf(r[d], head_w[d * 10 + j], a);
        out[(blockIdx.x * NSEQ + s) * 10 + j] = a;
    }
}

extern "C" void kernel_launch(void* const* d_in, const int* in_sizes, int n_in,
                              void* d_out, int out_size)
{
    const float* x       = (const float*)d_in[0];
    const float* embed_w = (const float*)d_in[1];
    const float* embed_b = (const float*)d_in[2];
    const float* ln1_g   = (const float*)d_in[3];
    const float* ln1_b   = (const float*)d_in[4];
    const float* qkv_w   = (const float*)d_in[5];
    const float* proj_w  = (const float*)d_in[6];
    const float* ln2_g   = (const float*)d_in[7];
    const float* ln2_b   = (const float*)d_in[8];
    const float* ffn_w1  = (const float*)d_in[9];
    const float* ffn_b1  = (const float*)d_in[10];
    const float* ffn_w2  = (const float*)d_in[11];
    const float* ffn_b2  = (const float*)d_in[12];
    const float* lnf_g   = (const float*)d_in[13];
    const float* lnf_b   = (const float*)d_in[14];
    const float* head_w  = (const float*)d_in[15];
    const float* head_b  = (const float*)d_in[16];
    float* out = (float*)d_out;

    int nTokens = in_sizes[0] / 4;       // B*T
    int nB = nTokens / TT;
    int grid = nB / NSEQ;                // 1024

    cudaFuncSetAttribute(waypoint_kernel,
                         cudaFuncAttributeMaxDynamicSharedMemorySize, SMEM_BYTES);

    waypoint_kernel<<<grid, NTHREADS, SMEM_BYTES>>>(
        x, embed_w, embed_b, ln1_g, ln1_b, qkv_w, proj_w,
        ln2_g, ln2_b, ffn_w1, ffn_b1, ffn_w2, ffn_b2,
        lnf_g, lnf_b, head_w, head_b, out);
}

// round 3
// speedup vs baseline: 1.3521x; 1.0300x over previous
#include <cuda_runtime.h>
#include <cuda_bf16.h>
#include <cstdint>

// Problem constants
#define BATCH   16384
#define TT      10
#define DD      64
#define HH      4
#define DH      16
#define LL      3
#define FF      256
#define NSEQ    16
#define MM      (NSEQ*TT)   // 160 rows per CTA
#define NTHREADS 512

// Shared memory layout (floats)
#define H_STR   68
#define B_STR   260
#define W_STR   66          // 66 mod 32 = 2 -> conflict-free LDS.64 across 16 lanes
#define H_ELEMS (MM*H_STR)
#define B_ELEMS (MM*B_STR)
#define W_ELEMS (64*W_STR)
#define SMEM_FLOATS (H_ELEMS + B_ELEMS + W_ELEMS)
#define SMEM_BYTES  (SMEM_FLOATS*4)   // 226816

// ---------------- packed f32x2 helpers ----------------
__device__ __forceinline__ void fma2(unsigned long long &d,
                                     unsigned long long a,
                                     unsigned long long b) {
    asm("fma.rn.f32x2 %0, %1, %2, %0;" : "+l"(d) : "l"(a), "l"(b));
}
__device__ __forceinline__ float2 unpack2(unsigned long long v) {
    float2 f;
    asm("mov.b64 {%0, %1}, %2;" : "=f"(f.x), "=f"(f.y) : "l"(v));
    return f;
}

// Fast exact-GELU: Abramowitz-Stegun 7.1.26 erf (|abs err| <= 1.5e-7)
__device__ __forceinline__ float gelu_fast(float v) {
    float t = fabsf(v) * 0.70710678118654752f;
    float u = __fdividef(1.0f, fmaf(0.3275911f, t, 1.0f));
    float p = fmaf(1.061405429f, u, -1.453152027f);
    p = fmaf(p, u, 1.421413741f);
    p = fmaf(p, u, -0.284496736f);
    p = fmaf(p, u, 0.254829592f);
    p *= u;
    float e = __expf(-t * t);
    float erf_abs = fmaf(-p, e, 1.0f);
    float sgn = copysignf(erf_abs, v);
    return 0.5f * v * (1.0f + sgn);
}

// 16-lane (half-warp) sum: lanes differing in bits 0..3 share a row
__device__ __forceinline__ float hsum16(float v) {
    v += __shfl_xor_sync(0xffffffffu, v, 1);
    v += __shfl_xor_sync(0xffffffffu, v, 2);
    v += __shfl_xor_sync(0xffffffffu, v, 4);
    v += __shfl_xor_sync(0xffffffffu, v, 8);
    return v;
}

// ---------------- weight tile prefetch (64x64) ----------------
struct WFrag { float4 v[2]; };

__device__ __forceinline__ WFrag fetch_w64(const float* __restrict__ g, int gStride) {
    WFrag f;
    int t = threadIdx.x;
#pragma unroll
    for (int i = 0; i < 2; i++) {
        int e  = t + i * NTHREADS;
        int k  = e >> 4;
        int c4 = e & 15;
        f.v[i] = *reinterpret_cast<const float4*>(g + k * gStride + c4 * 4);
    }
    return f;
}

__device__ __forceinline__ void commit_wt(const WFrag& f, float* __restrict__ wt) {
    int t = threadIdx.x;
#pragma unroll
    for (int i = 0; i < 2; i++) {
        int e  = t + i * NTHREADS;
        int k  = e >> 4;
        int j0 = (e & 15) * 4;
        wt[(j0 + 0) * W_STR + k] = f.v[i].x;
        wt[(j0 + 1) * W_STR + k] = f.v[i].y;
        wt[(j0 + 2) * W_STR + k] = f.v[i].z;
        wt[(j0 + 3) * W_STR + k] = f.v[i].w;
    }
}

// ---------------- GEMM tile: [160 x 64] += / = A[160 x 64] * W[64 x 64] ----------
// tr = tid>>4 (0..31) -> 5 rows; tc = tid&15 -> cols {tc, tc+16, tc+32, tc+48}
// Optional fused LayerNorm of the (accumulated) output rows via half-warp shfl.
template<bool GELU, bool ACC, bool LNFUSE>
__device__ __forceinline__ void gemm_tile(
    const float* __restrict__ Asm, int aStr,
    const float* __restrict__ wt,
    float* __restrict__ Osm, int oStr,
    const float* __restrict__ bias,      // nullptr if none
    float* __restrict__ lnDst, int lnStr,
    const float* __restrict__ lnG, const float* __restrict__ lnB)
{
    const int tr = threadIdx.x >> 4;
    const int tc = threadIdx.x & 15;
    const float* A0 = Asm + (tr * 5) * aStr;

    unsigned long long acc[5][4];
#pragma unroll
    for (int u = 0; u < 5; u++)
#pragma unroll
        for (int c = 0; c < 4; c++) acc[u][c] = 0ULL;

#pragma unroll 8
    for (int k4 = 0; k4 < 16; k4++) {
        unsigned long long a0[5], a1[5];
#pragma unroll
        for (int u = 0; u < 5; u++) {
            ulonglong2 av = *reinterpret_cast<const ulonglong2*>(A0 + u * aStr + k4 * 4);
            a0[u] = av.x;
            a1[u] = av.y;
        }
#pragma unroll
        for (int c = 0; c < 4; c++) {
            const float* wr = wt + (tc + 16 * c) * W_STR + k4 * 4;
            unsigned long long w0 = *reinterpret_cast<const unsigned long long*>(wr);
            unsigned long long w1 = *reinterpret_cast<const unsigned long long*>(wr + 2);
#pragma unroll
            for (int u = 0; u < 5; u++) {
                fma2(acc[u][c], a0[u], w0);
                fma2(acc[u][c], a1[u], w1);
            }
        }
    }

    float bv[4], gv[4], bbv[4];
#pragma unroll
    for (int c = 0; c < 4; c++) {
        int j = tc + 16 * c;
        bv[c]  = bias ? bias[j] : 0.f;
        if (LNFUSE) { gv[c] = lnG[j]; bbv[c] = lnB[j]; }
    }

#pragma unroll
    for (int u = 0; u < 5; u++) {
        float* orow = Osm + (tr * 5 + u) * oStr;
        float hv[4];
#pragma unroll
        for (int c = 0; c < 4; c++) {
            int j = tc + 16 * c;
            float2 v = unpack2(acc[u][c]);
            float x = v.x + v.y + bv[c];
            if (GELU) x = gelu_fast(x);
            if (ACC)  x += orow[j];
            hv[c] = x;
            orow[j] = x;
        }
        if (LNFUSE) {
            float s  = hv[0] + hv[1] + hv[2] + hv[3];
            float s2 = hv[0]*hv[0] + hv[1]*hv[1] + hv[2]*hv[2] + hv[3]*hv[3];
            s  = hsum16(s);
            s2 = hsum16(s2);
            float m   = s * (1.f / DD);
            float inv = rsqrtf(s2 * (1.f / DD) - m * m + 1e-5f);
            float* lrow = lnDst + (tr * 5 + u) * lnStr;
#pragma unroll
            for (int c = 0; c < 4; c++) {
                int j = tc + 16 * c;
                lrow[j] = (hv[c] - m) * inv * gv[c] + bbv[c];
            }
        }
    }
}

__global__ __launch_bounds__(NTHREADS, 1)
void waypoint_kernel(
    const float* __restrict__ x,
    const float* __restrict__ embed_w, const float* __restrict__ embed_b,
    const float* __restrict__ ln1_g,   const float* __restrict__ ln1_b,
    const float* __restrict__ qkv_w,   const float* __restrict__ proj_w,
    const float* __restrict__ ln2_g,   const float* __restrict__ ln2_b,
    const float* __restrict__ ffn_w1,  const float* __restrict__ ffn_b1,
    const float* __restrict__ ffn_w2,  const float* __restrict__ ffn_b2,
    const float* __restrict__ lnf_g,   const float* __restrict__ lnf_b,
    const float* __restrict__ head_w,  const float* __restrict__ head_b,
    float* __restrict__ out)
{
    extern __shared__ float sm[];
    float* h   = sm;                 // [160][68]
    float* buf = sm + H_ELEMS;       // [160][260]
    float* wt  = buf + B_ELEMS;      // [64][66] transposed weight tile

    const int tid = threadIdx.x;
    const int rowBase = blockIdx.x * MM;

    // -------- embed (+ fused ln1 of layer 0 -> buf[:,192:256]) --------
    {
        const float4* X4 = reinterpret_cast<const float4*>(x);
        const float4* W4 = reinterpret_cast<const float4*>(embed_w);
        const float4* B4 = reinterpret_cast<const float4*>(embed_b);
        const float4* G4 = reinterpret_cast<const float4*>(ln1_g);
        const float4* LB4 = reinterpret_cast<const float4*>(ln1_b);
#pragma unroll
        for (int it = 0; it < 5; it++) {
            int idx = tid + it * NTHREADS;       // 0..2559
            int r = idx >> 4, d4 = idx & 15;
            float4 xv = X4[rowBase + r];
            float4 w0 = W4[d4], w1 = W4[16 + d4], w2 = W4[32 + d4], w3 = W4[48 + d4];
            float4 v = B4[d4];
            v.x = fmaf(xv.x, w0.x, fmaf(xv.y, w1.x, fmaf(xv.z, w2.x, fmaf(xv.w, w3.x, v.x))));
            v.y = fmaf(xv.x, w0.y, fmaf(xv.y, w1.y, fmaf(xv.z, w2.y, fmaf(xv.w, w3.y, v.y))));
            v.z = fmaf(xv.x, w0.z, fmaf(xv.y, w1.z, fmaf(xv.z, w2.z, fmaf(xv.w, w3.z, v.z))));
            v.w = fmaf(xv.x, w0.w, fmaf(xv.y, w1.w, fmaf(xv.z, w2.w, fmaf(xv.w, w3.w, v.w))));
            *reinterpret_cast<float4*>(h + r * H_STR + d4 * 4) = v;
            // fused layer-0 ln1
            float s  = v.x + v.y + v.z + v.w;
            float s2 = v.x*v.x + v.y*v.y + v.z*v.z + v.w*v.w;
            s  = hsum16(s);
            s2 = hsum16(s2);
            float m   = s * (1.f / DD);
            float inv = rsqrtf(s2 * (1.f / DD) - m * m + 1e-5f);
            float4 gvv = G4[d4], bvv = LB4[d4];
            float4 o;
            o.x = (v.x - m) * inv * gvv.x + bvv.x;
            o.y = (v.y - m) * inv * gvv.y + bvv.y;
            o.z = (v.z - m) * inv * gvv.z + bvv.z;
            o.w = (v.w - m) * inv * gvv.w + bvv.w;
            *reinterpret_cast<float4*>(buf + 192 + r * B_STR + d4 * 4) = o;
        }
    }
    __syncthreads();

    WFrag wf = fetch_w64(qkv_w, 3 * DD);

    for (int i = 0; i < LL; i++) {
        const float* l_qkv = qkv_w  + i * DD * 3 * DD;
        const float* l_prj = proj_w + i * DD * DD;
        const float* l_w1  = ffn_w1 + i * DD * FF;
        const float* l_w2  = ffn_w2 + i * FF * DD;

        // -------- qkv: buf[:,0:192] = ln1 @ qkv_w --------
        for (int nt = 0; nt < 3; nt++) {
            commit_wt(wf, wt);
            __syncthreads();
            if (nt < 2)  wf = fetch_w64(l_qkv + (nt + 1) * 64, 3 * DD);
            else         wf = fetch_w64(l_prj, DD);
            gemm_tile<false,false,false>(buf + 192, B_STR, wt, buf + nt * 64, B_STR,
                                         nullptr, nullptr, 0, nullptr, nullptr);
            __syncthreads();
        }

        // -------- attention (causal, T=10, dh=16), float4 --------
        {
            int pair = tid >> 3;
            int sub  = tid & 7;
            int s  = pair >> 2;
            int hd = pair & 3;
            const float4* qb = reinterpret_cast<const float4*>(buf + hd * DH);
            const float4* kb = reinterpret_cast<const float4*>(buf + 64  + hd * DH);
            const float4* vb = reinterpret_cast<const float4*>(buf + 128 + hd * DH);
            float4* yb = reinterpret_cast<float4*>(buf + 192 + hd * DH);
            const int RS = B_STR / 4;   // 65

            for (int q = sub; q < TT; q += 8) {
                int rq = s * TT + q;
                float4 qv[4];
#pragma unroll
                for (int d = 0; d < 4; d++) qv[d] = qb[rq * RS + d];

                float sc[TT];
                float mx = -1e30f;
                for (int kk = 0; kk <= q; kk++) {
                    const float4* kr = kb + (s * TT + kk) * RS;
                    float a = 0.f;
#pragma unroll
                    for (int d = 0; d < 4; d++) {
                        float4 kv = kr[d];
                        a = fmaf(qv[d].x, kv.x, a);
                        a = fmaf(qv[d].y, kv.y, a);
                        a = fmaf(qv[d].z, kv.z, a);
                        a = fmaf(qv[d].w, kv.w, a);
                    }
                    a *= 0.25f;
                    sc[kk] = a;
                    mx = fmaxf(mx, a);
                }
                float ssum = 0.f;
                for (int kk = 0; kk <= q; kk++) {
                    sc[kk] = __expf(sc[kk] - mx);
                    ssum += sc[kk];
                }
                float inv = __fdividef(1.f, ssum);
                float4 y[4];
#pragma unroll
                for (int d = 0; d < 4; d++) y[d] = make_float4(0.f, 0.f, 0.f, 0.f);
                for (int kk = 0; kk <= q; kk++) {
                    float a = sc[kk] * inv;
                    const float4* vr = vb + (s * TT + kk) * RS;
#pragma unroll
                    for (int d = 0; d < 4; d++) {
                        float4 vv = vr[d];
                        y[d].x = fmaf(a, vv.x, y[d].x);
                        y[d].y = fmaf(a, vv.y, y[d].y);
                        y[d].z = fmaf(a, vv.z, y[d].z);
                        y[d].w = fmaf(a, vv.w, y[d].w);
                    }
                }
#pragma unroll
                for (int d = 0; d < 4; d++) yb[rq * RS + d] = y[d];
            }
        }
        __syncthreads();

        // -------- proj: h += y @ proj_w  (+ fused ln2 -> buf[:,0:64]) --------
        commit_wt(wf, wt);
        __syncthreads();
        wf = fetch_w64(l_w1, FF);
        gemm_tile<false,true,true>(buf + 192, B_STR, wt, h, H_STR, nullptr,
                                   buf, B_STR, ln2_g + i * DD, ln2_b + i * DD);
        __syncthreads();

        // -------- FFN, N tiled 4x64 --------
        for (int ft = 0; ft < 4; ft++) {
            // z = gelu(ln2 @ w1 + b1) -> buf[:,64:128]
            commit_wt(wf, wt);
            __syncthreads();
            wf = fetch_w64(l_w2 + ft * 64 * DD, DD);
            gemm_tile<true,false,false>(buf, B_STR, wt, buf + 64, B_STR,
                                        ffn_b1 + i * FF + ft * 64,
                                        nullptr, 0, nullptr, nullptr);
            __syncthreads();

            // h += z @ w2 (+ b2 at ft==0; fused LN at ft==3)
            commit_wt(wf, wt);
            __syncthreads();
            if (ft < 3)      wf = fetch_w64(l_w1 + (ft + 1) * 64, FF);
            else if (i < 2)  wf = fetch_w64(qkv_w + (i + 1) * DD * 3 * DD, 3 * DD);
            else             wf = fetch_w64(qkv_w, 3 * DD);
            const float* b2 = (ft == 0) ? (ffn_b2 + i * DD) : nullptr;
            if (ft < 3) {
                gemm_tile<false,true,false>(buf + 64, B_STR, wt, h, H_STR, b2,
                                            nullptr, 0, nullptr, nullptr);
            } else if (i < 2) {
                // fused ln1 of next layer -> buf[:,192:256]
                gemm_tile<false,true,true>(buf + 64, B_STR, wt, h, H_STR, b2,
                                           buf + 192, B_STR,
                                           ln1_g + (i + 1) * DD, ln1_b + (i + 1) * DD);
            } else {
                // fused final LN -> buf[:,0:64]
                gemm_tile<false,true,true>(buf + 64, B_STR, wt, h, H_STR, b2,
                                           buf, B_STR, lnf_g, lnf_b);
            }
            __syncthreads();
        }
    }

    // -------- head: out[s, j] = lnf[last token] @ head_w + head_b --------
    if (tid < NSEQ * 10) {
        int s = tid / 10;
        int j = tid % 10;
        const float* r = buf + (s * TT + TT - 1) * B_STR;
        float a = head_b[j];
#pragma unroll 16
        for (int d = 0; d < DD; d++) a = fmaf(r[d], head_w[d * 10 + j], a);
        out[(blockIdx.x * NSEQ + s) * 10 + j] = a;
    }
}

extern "C" void kernel_launch(void* const* d_in, const int* in_sizes, int n_in,
                              void* d_out, int out_size)
{
    const float* x       = (const float*)d_in[0];
    const float* embed_w = (const float*)d_in[1];
    const float* embed_b = (const float*)d_in[2];
    const float* ln1_g   = (const float*)d_in[3];
    const float* ln1_b   = (const float*)d_in[4];
    const float* qkv_w   = (const float*)d_in[5];
    const float* proj_w  = (const float*)d_in[6];
    const float* ln2_g   = (const float*)d_in[7];
    const float* ln2_b   = (const float*)d_in[8];
    const float* ffn_w1  = (const float*)d_in[9];
    const float* ffn_b1  = (const float*)d_in[10];
    const float* ffn_w2  = (const float*)d_in[11];
    const float* ffn_b2  = (const float*)d_in[12];
    const float* lnf_g   = (const float*)d_in[13];
    const float* lnf_b   = (const float*)d_in[14];
    const float* head_w  = (const float*)d_in[15];
    const float* head_b  = (const float*)d_in[16];
    float* out = (float*)d_out;

    int nTokens = in_sizes[0] / 4;
    int nB = nTokens / TT;
    int grid = nB / NSEQ;

    cudaFuncSetAttribute(waypoint_kernel,
                         cudaFuncAttributeMaxDynamicSharedMemorySize, SMEM_BYTES);

    waypoint_kernel<<<grid, NTHREADS, SMEM_BYTES>>>(
        x, embed_w, embed_b, ln1_g, ln1_b, qkv_w, proj_w,
        ln2_g, ln2_b, ffn_w1, ffn_b1, ffn_w2, ffn_b2,
        lnf_g, lnf_b, head_w, head_b, out);
}